// round 17
// baseline (speedup 1.0000x reference)
#include <cuda_runtime.h>
#include <cuda_bf16.h>
#include <math.h>

// Problem constants
#define ROWS_TOTAL 32768
#define K_DIM 1024
#define ANCHORS 8
#define PRED_ELEMS (ROWS_TOTAL * ANCHORS)   // 262144

// CTA = 512 thr = 16 warps = 8 warp-pairs. Pair P owns 4 rows; within a pair,
// warp h=wid&1 computes anchor-pairs h*4..h*4+3 (8 outputs). Block: 32 rows.
#define THREADS 512
#define WARPS_PER_BLOCK 16
#define ROWS_PER_WARP 4
#define ROWS_PER_BLOCK 32
#define NBLOCKS (ROWS_TOTAL / ROWS_PER_BLOCK)   // 1024
#define NCHUNKS 32                              // K chunks of 32
#define DP 4                                    // X register-prefetch depth

// W transposed in smem: Wt[pair p][k] = (W[k][2p], W[k][2p+1]) as u64.
// 8 * 1024 * 8B = 64KB, no padding. LDS.64: lane L -> banks {2L, 2L+1};
// a 16-lane phase tiles all 32 banks exactly once -> conflict-free.
#define WT_U64 (ANCHORS * K_DIM)
#define SMEM_BYTES (WT_U64 * 8)                 // 65536

__device__ float g_part_nll[NBLOCKS];
__device__ int   g_part_cnt[NBLOCKS];
__device__ unsigned int g_done;   // zero-init; finalizer resets -> replay-safe

__device__ __forceinline__ void fma2(unsigned long long& d,
                                     unsigned long long a,
                                     unsigned long long b) {
    asm("fma.rn.f32x2 %0, %1, %2, %0;" : "+l"(d) : "l"(a), "l"(b));
}
__device__ __forceinline__ unsigned long long add2r(unsigned long long a,
                                                    unsigned long long b) {
    asm("add.rn.f32x2 %0, %0, %1;" : "+l"(a) : "l"(b));
    return a;
}
__device__ __forceinline__ unsigned long long pack_dup(float x) {
    unsigned long long r;
    asm("mov.b64 %0, {%1, %1};" : "=l"(r) : "r"(__float_as_uint(x)));
    return r;
}
__device__ __forceinline__ unsigned long long pack2(float lo, float hi) {
    unsigned long long r;
    asm("mov.b64 %0, {%1, %2};" : "=l"(r)
        : "r"(__float_as_uint(lo)), "r"(__float_as_uint(hi)));
    return r;
}
__device__ __forceinline__ void unpack2(unsigned long long v, float& lo, float& hi) {
    unsigned int l, h;
    asm("mov.b64 {%0, %1}, %2;" : "=r"(l), "=r"(h) : "l"(v));
    lo = __uint_as_float(l);
    hi = __uint_as_float(h);
}

__global__ __launch_bounds__(THREADS, 1)
void rpn_main_kernel(const float*  __restrict__ Xf,     // [32768][1024]
                     const float*  __restrict__ Wg,     // [1024][16]
                     const float*  __restrict__ bias,   // [16]
                     const int*    __restrict__ labels, // [32768][8]
                     float* __restrict__ out)
{
    extern __shared__ __align__(16) unsigned long long Wt[];  // [8][1024] u64
    __shared__ float s_nll[WARPS_PER_BLOCK];
    __shared__ int   s_cnt[WARPS_PER_BLOCK];
    __shared__ int   s_last;

    const int tid  = threadIdx.x;
    const int wid  = tid >> 5;
    const int lane = tid & 31;
    const int h    = wid & 1;             // anchor half
    const int pairI = wid >> 1;           // 0..7
    const int wrow0 = blockIdx.x * ROWS_PER_BLOCK + pairI * ROWS_PER_WARP;

    // X base: lane's column within this warp's 4 rows (coalesced 128B/row LDG)
    const float* gx = Xf + (size_t)wrow0 * K_DIM + lane;

    // Register prefetch: chunks 0..DP-1 issued before W staging completes,
    // so DRAM latency overlaps STS + syncthreads.
    float xp[DP][ROWS_PER_WARP];
#pragma unroll
    for (int j = 0; j < DP; ++j)
#pragma unroll
        for (int r = 0; r < ROWS_PER_WARP; ++r)
            xp[j][r] = gx[(size_t)r * K_DIM + j * 32];

    // Stage W transposed: read float4 (coalesced), write two u64 pairs.
    {
        const float4* Wg4 = reinterpret_cast<const float4*>(Wg);
        for (int i = tid; i < K_DIM * 4; i += THREADS) {
            const int k = i >> 2;
            const int q = i & 3;          // float4 q covers pairs 2q, 2q+1
            const float4 v = Wg4[i];
            Wt[(2 * q) * K_DIM + k]     = pack2(v.x, v.y);
            Wt[(2 * q + 1) * K_DIM + k] = pack2(v.z, v.w);
        }
    }
    __syncthreads();   // W visible to all warps

    const unsigned long long* wt = Wt + h * 4 * K_DIM;   // this warp's 4 pairs

    // acc[r*4 + pj] packs (anchor h*4+pj: class0, class1) for local row r
    unsigned long long acc[16];
#pragma unroll
    for (int j = 0; j < 16; ++j) acc[j] = 0ULL;

    // Main: outer cc = 0,4,..,24 — compute chunk cc+j from xp[j], refill with cc+j+DP.
#pragma unroll 1
    for (int cc = 0; cc < NCHUNKS - DP; cc += DP) {
#pragma unroll
        for (int j = 0; j < DP; ++j) {
            const int c = cc + j;
            const int k = c * 32 + lane;
            // consume current values into temps, then issue refill LDGs early
            float xs[ROWS_PER_WARP];
#pragma unroll
            for (int r = 0; r < ROWS_PER_WARP; ++r) xs[r] = xp[j][r];
#pragma unroll
            for (int r = 0; r < ROWS_PER_WARP; ++r)
                xp[j][r] = gx[(size_t)r * K_DIM + (c + DP) * 32];

            const unsigned long long w0 = wt[0 * K_DIM + k];
            const unsigned long long w1 = wt[1 * K_DIM + k];
            const unsigned long long w2 = wt[2 * K_DIM + k];
            const unsigned long long w3 = wt[3 * K_DIM + k];
#pragma unroll
            for (int r = 0; r < ROWS_PER_WARP; ++r) {
                const unsigned long long xx = pack_dup(xs[r]);
                fma2(acc[r * 4 + 0], xx, w0);
                fma2(acc[r * 4 + 1], xx, w1);
                fma2(acc[r * 4 + 2], xx, w2);
                fma2(acc[r * 4 + 3], xx, w3);
            }
        }
    }
    // Tail: chunks 28..31 already in registers
#pragma unroll
    for (int j = 0; j < DP; ++j) {
        const int c = NCHUNKS - DP + j;
        const int k = c * 32 + lane;
        const unsigned long long w0 = wt[0 * K_DIM + k];
        const unsigned long long w1 = wt[1 * K_DIM + k];
        const unsigned long long w2 = wt[2 * K_DIM + k];
        const unsigned long long w3 = wt[3 * K_DIM + k];
#pragma unroll
        for (int r = 0; r < ROWS_PER_WARP; ++r) {
            const unsigned long long xx = pack_dup(xp[j][r]);
            fma2(acc[r * 4 + 0], xx, w0);
            fma2(acc[r * 4 + 1], xx, w1);
            fma2(acc[r * 4 + 2], xx, w2);
            fma2(acc[r * 4 + 3], xx, w3);
        }
    }

    // Reduction: 16 packed values over 32 lanes.
    // Pre-level folds the two half-warps (after it, lanes L and L+16 identical).
#pragma unroll
    for (int i = 0; i < 16; ++i)
        acc[i] = add2r(acc[i], __shfl_xor_sync(0xffffffffu, acc[i], 16));
    // 4 butterfly levels on 16 values within each 16-lane group:
    // afterwards lane L owns value j = L&15.
#pragma unroll
    for (int lvl = 0; lvl < 4; ++lvl) {
        const int m = 8 >> lvl;
        const bool up = (lane & m) != 0;
#pragma unroll
        for (int i = 0; i < 8; ++i) {
            if (i >= m) continue;
            const unsigned long long sent = up ? acc[i] : acc[m + i];
            const unsigned long long rcv = __shfl_xor_sync(0xffffffffu, sent, m);
            acc[i] = up ? add2r(acc[m + i], rcv) : add2r(acc[i], rcv);
        }
    }

    // Epilogue: lanes 0..15 own distinct results; lanes 16..31 are duplicates.
    const int j15 = lane & 15;
    const int r_loc = j15 >> 2;
    const int a = h * 4 + (j15 & 3);
    const int row = wrow0 + r_loc;
    const bool owner = (lane < 16);

    float l0, l1;
    unpack2(acc[0], l0, l1);
    l0 += __ldg(&bias[2 * a]);
    l1 += __ldg(&bias[2 * a + 1]);

    const int lab = owner ? __ldg(&labels[row * ANCHORS + a]) : -1;
    const bool valid = (lab != -1);
    const int pred = (l1 > l0) ? 1 : 0;   // argmax, tie -> 0

    const float mx = fmaxf(l0, l1);
    const float mn = fminf(l0, l1);
    const float lse = mx + log1pf(expf(mn - mx));
    const float picked = (lab > 0) ? l1 : l0;   // clamp(-1)->0 picks l0
    const float nll = valid ? (lse - picked) : 0.0f;

    if (owner) {
        const int idx = row * ANCHORS + a;
        out[1 + idx] = (float)pred;
        out[1 + PRED_ELEMS + idx] = (pred == 1 && valid) ? 1.0f : 0.0f;
    }

    // Loss: warp -> block -> per-block partial (non-owners contribute 0)
    float nll_w = nll;
    int cnt_w = valid ? 1 : 0;
#pragma unroll
    for (int s = 16; s > 0; s >>= 1) {
        nll_w += __shfl_xor_sync(0xffffffffu, nll_w, s);
        cnt_w += __shfl_xor_sync(0xffffffffu, cnt_w, s);
    }
    if (lane == 0) { s_nll[wid] = nll_w; s_cnt[wid] = cnt_w; }
    __syncthreads();

    if (tid == 0) {
        float bn = 0.f; int bc = 0;
#pragma unroll
        for (int i = 0; i < WARPS_PER_BLOCK; ++i) { bn += s_nll[i]; bc += s_cnt[i]; }
        g_part_nll[blockIdx.x] = bn;
        g_part_cnt[blockIdx.x] = bc;
        __threadfence();
        const unsigned int old = atomicAdd(&g_done, 1u);
        s_last = (old == NBLOCKS - 1) ? 1 : 0;
    }
    __syncthreads();

    // Last-arriving block performs the final loss reduction (no extra launch).
    if (s_last) {
        __shared__ double f_sum[WARPS_PER_BLOCK];
        __shared__ int    f_cnt[WARPS_PER_BLOCK];
        double sum = 0.0;
        int cnt = 0;
#pragma unroll
        for (int i = 0; i < NBLOCKS / THREADS; ++i) {
            const int bidx = tid + i * THREADS;
            sum += (double)g_part_nll[bidx];
            cnt += g_part_cnt[bidx];
        }
#pragma unroll
        for (int s = 16; s > 0; s >>= 1) {
            sum += __shfl_xor_sync(0xffffffffu, sum, s);
            cnt += __shfl_xor_sync(0xffffffffu, cnt, s);
        }
        if (lane == 0) { f_sum[wid] = sum; f_cnt[wid] = cnt; }
        __syncthreads();
        if (tid == 0) {
            double t = 0.0; int c = 0;
#pragma unroll
            for (int i = 0; i < WARPS_PER_BLOCK; ++i) { t += f_sum[i]; c += f_cnt[i]; }
            const double denom = c > 1 ? (double)c : 1.0;
            out[0] = (float)(t / denom);
            g_done = 0u;   // reset for next graph replay
        }
    }
}

extern "C" void kernel_launch(void* const* d_in, const int* in_sizes, int n_in,
                              void* d_out, int out_size) {
    const float* Xf = (const float*)d_in[0];   // batch_input (64,512,1024) f32
    const float* Wg = (const float*)d_in[1];   // W (1024,16) f32
    const float* b  = (const float*)d_in[2];   // b (16,) f32
    const int*   lb = (const int*)d_in[3];     // anchor_labels (64,512,8) i32
    float* out = (float*)d_out;

    cudaFuncSetAttribute(rpn_main_kernel,
                         cudaFuncAttributeMaxDynamicSharedMemorySize, SMEM_BYTES);
    rpn_main_kernel<<<NBLOCKS, THREADS, SMEM_BYTES>>>(Xf, Wg, b, lb, out);
}